// round 12
// baseline (speedup 1.0000x reference)
#include <cuda_runtime.h>
#include <cstdint>

// PatchNeighborSearcher: B=8, H=W=16 (P=256), L=64, C=64.
// out[b, p, l*8+n, c] = in[b, neighbor_p(n), l, c] if in-bounds else 0.
//
// R4 gather structure (best steady-state) made persistent: grid = one wave
// (148 SMs x 8 CTAs), each thread grid-strides over ~7 work chunks. Removes
// ~6 wave transitions and keeps the LDG/STG pipeline primed across chunks.
//
// Per work-item (one per (b,l,h,w,c4)): 8 predicated LDG.128 (MLP=8) +
// 8 coalesced STG.128 evict-first.
//
// Input  float4 idx: (b<<18)|(h<<14)|(w<<10)|(l<<4)|c4
// Output float4 idx: (b<<21)|(h<<17)|(w<<13)|(l<<7)|(n<<4)|c4

#define TOTAL_ITEMS (8 * 64 * 16 * 16 * 16)   // 2,097,152

__global__ void __launch_bounds__(256) patch_neighbor_kernel(
    const float4* __restrict__ in, float4* __restrict__ out)
{
    const int stride = gridDim.x * blockDim.x;
    const float4 zero = make_float4(0.f, 0.f, 0.f, 0.f);

    // neighbor offset in float4 units: (dy*16 + dx) << 10
    const int OFF[8] = {
        (-17) << 10, (-16) << 10, (-15) << 10,
        ( -1) << 10,               (  1) << 10,
        ( 15) << 10, ( 16) << 10, ( 17) << 10
    };

    for (int tid = blockIdx.x * blockDim.x + threadIdx.x;
         tid < TOTAL_ITEMS; tid += stride)
    {
        int c4 = tid & 15;
        int w  = (tid >> 4) & 15;
        int h  = (tid >> 8) & 15;
        int l  = (tid >> 12) & 63;
        int b  = tid >> 18;

        int hm = (h > 0);
        int hp = (h < 15);
        int wm = (w > 0);
        int wp = (w < 15);

        // neighbor order: (-1,-1)(-1,0)(-1,1)(0,-1)(0,1)(1,-1)(1,0)(1,1)
        int valid[8] = { hm & wm, hm, hm & wp,
                         wm,          wp,
                         hp & wm, hp, hp & wp };

        int ibase = (b << 18) | (h << 14) | (w << 10) | (l << 4) | c4;
        int obase = (b << 21) | (h << 17) | (w << 13) | (l << 7) | c4;

        float4 v[8];
        #pragma unroll
        for (int n = 0; n < 8; n++) {
            v[n] = valid[n] ? __ldg(&in[ibase + OFF[n]]) : zero;
        }

        #pragma unroll
        for (int n = 0; n < 8; n++) {
            __stcs(&out[obase + (n << 4)], v[n]);
        }
    }
}

extern "C" void kernel_launch(void* const* d_in, const int* in_sizes, int n_in,
                              void* d_out, int out_size)
{
    const float4* in = (const float4*)d_in[0];
    float4* out = (float4*)d_out;

    int grid = 148 * 8;    // one full wave at 8 CTAs/SM (256 thr, 28 regs)
    patch_neighbor_kernel<<<grid, 256>>>(in, out);
}

// round 13
// speedup vs baseline: 1.0367x; 1.0367x over previous
#include <cuda_runtime.h>
#include <cstdint>

// PatchNeighborSearcher: B=8, H=W=16 (P=256), L=64, C=64.
// out[b, p, l*8+n, c] = in[b, neighbor_p(n), l, c] if in-bounds else 0.
//
// Write-locality mapping: block = fixed (b, h, w, l-quarter); threads =
// 16 l x 16 c4. Each block stores a single CONTIGUOUS 32KB output span
// (vs 16 scattered 2KB chunks in the previous mapping) -> maximal DRAM
// row-buffer locality on the 256MB write stream. valid[] is block-uniform
// (h, w fixed) so all load predication is divergence-free.
//
// Input  float4 idx: (b<<18)|(h<<14)|(w<<10)|(l<<4)|c4
// Output float4 idx: (b<<21)|(h<<17)|(w<<13)|(l<<7)|(n<<4)|c4

__global__ void __launch_bounds__(256) patch_neighbor_kernel(
    const float4* __restrict__ in, float4* __restrict__ out)
{
    int bid = blockIdx.x;            // (b<<10)|(h<<6)|(w<<2)|lq
    int lq = bid & 3;
    int w  = (bid >> 2) & 15;
    int h  = (bid >> 6) & 15;
    int b  = bid >> 10;

    int t  = threadIdx.x;
    int c4 = t & 15;
    int l  = (lq << 4) | (t >> 4);

    int hm = (h > 0);
    int hp = (h < 15);
    int wm = (w > 0);
    int wp = (w < 15);

    // neighbor order: (-1,-1)(-1,0)(-1,1)(0,-1)(0,1)(1,-1)(1,0)(1,1)
    // uniform across the block (h, w fixed)
    int valid[8] = { hm & wm, hm, hm & wp,
                     wm,          wp,
                     hp & wm, hp, hp & wp };

    // neighbor offset in float4 units: (dy*16 + dx) << 10
    const int OFF[8] = {
        (-17) << 10, (-16) << 10, (-15) << 10,
        ( -1) << 10,               (  1) << 10,
        ( 15) << 10, ( 16) << 10, ( 17) << 10
    };

    int ibase = (b << 18) | (h << 14) | (w << 10) | (l << 4) | c4;
    int obase = (b << 21) | (h << 17) | (w << 13) | (l << 7) | c4;

    const float4 zero = make_float4(0.f, 0.f, 0.f, 0.f);
    float4 v[8];

    #pragma unroll
    for (int n = 0; n < 8; n++) {
        v[n] = valid[n] ? __ldg(&in[ibase + OFF[n]]) : zero;
    }

    #pragma unroll
    for (int n = 0; n < 8; n++) {
        __stcs(&out[obase + (n << 4)], v[n]);
    }
}

extern "C" void kernel_launch(void* const* d_in, const int* in_sizes, int n_in,
                              void* d_out, int out_size)
{
    const float4* in = (const float4*)d_in[0];
    float4* out = (float4*)d_out;

    int grid = 8 * 16 * 16 * 4;   // (b, h, w, l-quarter) = 8192 blocks
    patch_neighbor_kernel<<<grid, 256>>>(in, out);
}

// round 14
// speedup vs baseline: 1.0625x; 1.0249x over previous
#include <cuda_runtime.h>
#include <cstdint>

// PatchNeighborSearcher: B=8, H=W=16 (P=256), L=64, C=64.
// out[b, p, l*8+n, c] = in[b, neighbor_p(n), l, c] if in-bounds else 0.
//
// FINAL (roofline) kernel — R4 design, dur champion across 13 variants.
// The problem is a pure ~256MB streaming-write drain: input (32MB) is
// L2-resident, all SM pipes <11%, and every structural alternative
// (v8 accesses, SMEM staging, TMA bulk stores, persistent grid, L2
// persistence hints, write-contiguity remaps) lands at the same
// ~5.35 TB/s sm_103a store ceiling.
//
// One thread per (b,l,h,w,c4): 8 predicated LDG.128 at compile-time
// constant offsets (MLP=8), 8 coalesced evict-first STG.128.
//
// Input  float4 idx: (b<<18)|(h<<14)|(w<<10)|(l<<4)|c4
// Output float4 idx: (b<<21)|(h<<17)|(w<<13)|(l<<7)|(n<<4)|c4

__global__ void __launch_bounds__(256) patch_neighbor_kernel(
    const float4* __restrict__ in, float4* __restrict__ out)
{
    int tid = blockIdx.x * blockDim.x + threadIdx.x;   // 2,097,152 threads

    int c4 = tid & 15;
    int w  = (tid >> 4) & 15;
    int h  = (tid >> 8) & 15;
    int l  = (tid >> 12) & 63;
    int b  = tid >> 18;

    int hm = (h > 0);
    int hp = (h < 15);
    int wm = (w > 0);
    int wp = (w < 15);

    // neighbor order: (-1,-1)(-1,0)(-1,1)(0,-1)(0,1)(1,-1)(1,0)(1,1)
    int valid[8] = { hm & wm, hm, hm & wp,
                     wm,          wp,
                     hp & wm, hp, hp & wp };

    // neighbor offset in float4 units: (dy*16 + dx) << 10
    constexpr int OFF[8] = {
        (-17) << 10, (-16) << 10, (-15) << 10,
        ( -1) << 10,               (  1) << 10,
        ( 15) << 10, ( 16) << 10, ( 17) << 10
    };

    int ibase = (b << 18) | (h << 14) | (w << 10) | (l << 4) | c4;
    int obase = (b << 21) | (h << 17) | (w << 13) | (l << 7) | c4;

    const float4 zero = make_float4(0.f, 0.f, 0.f, 0.f);
    float4 v[8];

    #pragma unroll
    for (int n = 0; n < 8; n++) {
        v[n] = valid[n] ? __ldg(&in[ibase + OFF[n]]) : zero;
    }

    #pragma unroll
    for (int n = 0; n < 8; n++) {
        __stcs(&out[obase + (n << 4)], v[n]);
    }
}

extern "C" void kernel_launch(void* const* d_in, const int* in_sizes, int n_in,
                              void* d_out, int out_size)
{
    const float4* in = (const float4*)d_in[0];
    float4* out = (float4*)d_out;

    int threads_total = (out_size / 4) / 8;   // 2,097,152
    int block = 256;
    int grid = (threads_total + block - 1) / block;
    patch_neighbor_kernel<<<grid, block>>>(in, out);
}